// round 13
// baseline (speedup 1.0000x reference)
#include <cuda_runtime.h>
#include <cstdint>

#define HGT    1024
#define WID    1024
#define TY     8                     // rows per slab unit (1 per warp)
#define RAD    5                     // 11x11 window radius
#define NROWS  (TY + 2 * RAD)        // 18 halo rows per slab
#define NUNITS 1024                  // 8 images * 128 slabs
#define GRID   592                   // 148 SMs * 4 CTAs: exactly resident
#define NPIX   (8.0 * 1024.0 * 1024.0)

__device__ float    g_part[NUNITS];
__device__ unsigned g_work = 0;
__device__ unsigned g_done = 0;

__global__ __launch_bounds__(256, 4)
void edge_loss_kernel(const float* __restrict__ x, const int* __restrict__ tgt,
                      float* __restrict__ out)
{
    const int lane = threadIdx.x & 31;
    const int warp = threadIdx.x >> 5;

    __shared__ uint2    s_ha[NROWS][32];         // .x = horiz OR, .y = horiz AND
    __shared__ unsigned s_tw[NROWS][32];
    __shared__ float    ws[8];
    __shared__ unsigned s_slab;
    __shared__ bool     amLast;

    for (;;) {
        if (threadIdx.x == 0) s_slab = atomicAdd(&g_work, 1u);
        __syncthreads();
        const unsigned s = s_slab;
        if (s >= NUNITS) break;

        const int b  = s >> 7;                   // image
        const int y0 = (s & 127) * TY;           // first row of slab

        // ---- Entry prefetch: this warp's x row, batches 0,1 ----
        const int y = y0 + warp;
        const float* xbase = x + (size_t)b * 2 * HGT * WID;
        const float4* x0r = (const float4*)(xbase + (size_t)y * WID);
        const float4* x1r = (const float4*)(xbase + (size_t)(HGT + y) * WID);
        float4 b0[2], b1[2];
        b0[0] = __ldcs(&x0r[lane]);
        b1[0] = __ldcs(&x1r[lane]);
        b0[1] = __ldcs(&x0r[lane + 32]);
        b1[1] = __ldcs(&x1r[lane + 32]);

        // ---- Phase A (cooperative): pack 18 halo rows, horiz OR/AND +-5 ----
        const int* tbase = tgt + (size_t)b * HGT * WID;
        #pragma unroll
        for (int i = warp; i < NROWS; i += 8) {
            int row = y0 - RAD + i;
            unsigned w = 0u;
            if (row >= 0 && row < HGT) {
                const uint4* p = (const uint4*)(tbase + (size_t)row * WID + lane * 32);
                #pragma unroll
                for (int q = 0; q < 8; q++) {
                    uint4 u = p[q];              // target values are 0 or 1
                    unsigned nib = u.x | (u.y << 1) | (u.z << 2) | (u.w << 3);
                    w |= nib << (4 * q);
                }
            }
            unsigned wl = __shfl_up_sync(0xffffffffu, w, 1);
            unsigned wr = __shfl_down_sync(0xffffffffu, w, 1);
            if (lane == 0)  wl = 0u;             // zero padding left
            if (lane == 31) wr = 0u;             // zero padding right
            unsigned o = w, a = w;
            #pragma unroll
            for (int sh = 1; sh <= RAD; sh++) {
                unsigned r = __funnelshift_r(w, wr, sh);
                unsigned l = __funnelshift_l(wl, w, sh);
                o |= r | l;
                a &= r & l;
            }
            s_tw[i][lane] = w;
            s_ha[i][lane] = make_uint2(o, a);
        }
        __syncthreads();

        // ---- Vertical combine from smem (this warp's row) ----
        uint2 h0 = s_ha[warp][lane];
        unsigned vo = h0.x, va = h0.y;
        #pragma unroll
        for (int d = 1; d <= 2 * RAD; d++) {
            uint2 hh = s_ha[warp + d][lane];
            vo |= hh.x;
            va &= hh.y;
        }
        unsigned ew = vo ^ va;                   // edge: window not uniform
        unsigned tc = s_tw[warp + RAD][lane];    // center target bits

        // ---- Assemble per-lane bit words: bit 4k+j = col 128k+4*lane+j ----
        unsigned ebits = 0u, tbits = 0u;
        const int src0 = lane >> 3, shb = 4 * (lane & 7);
        #pragma unroll
        for (int k = 0; k < 8; k++) {
            unsigned e = __shfl_sync(0xffffffffu, ew, 4 * k + src0);
            unsigned t = __shfl_sync(0xffffffffu, tc, 4 * k + src0);
            ebits |= ((e >> shb) & 0xFu) << (4 * k);
            tbits |= ((t >> shb) & 0xFu) << (4 * k);
        }

        // ---- Phase B: 8 k-iterations, depth-2 rolling prefetch ----
        float acc = 0.0f;
        #pragma unroll
        for (int m = 0; m < 8; m++) {
            const int cur = m & 1;
            float4 v0 = b0[cur];
            float4 v1 = b1[cur];
            if (m < 6) {                         // prefetch iteration m+2
                b0[cur] = __ldcs(&x0r[lane + 32 * (m + 2)]);
                b1[cur] = __ldcs(&x1r[lane + 32 * (m + 2)]);
            }
            const int base = 4 * m;
            #pragma unroll
            for (int j = 0; j < 4; j++) {
                float a0 = (&v0.x)[j];
                float a1 = (&v1.x)[j];
                unsigned tbit = (tbits >> (base + j)) & 1u;
                unsigned ebit = (ebits >> (base + j)) & 1u;
                float xt = tbit ? a1 : a0;
                float xo = tbit ? a0 : a1;
                float mx  = fmaxf(a0, a1);
                float lse = mx + __logf(1.0f + __expf(-fabsf(a0 - a1)));
                float c_off = xt - lse;
                float c_on  = 0.95f * xt + 0.1f * xo - 1.05f * lse;
                acc += ebit ? c_on : c_off;
            }
        }

        // ---- block reduction -> per-slab partial (deterministic) ----
        #pragma unroll
        for (int o = 16; o > 0; o >>= 1)
            acc += __shfl_xor_sync(0xffffffffu, acc, o);
        if (lane == 0) ws[warp] = acc;
        __syncthreads();
        if (threadIdx.x == 0) {
            float t = 0.0f;
            #pragma unroll
            for (int i = 0; i < 8; i++) t += ws[i];
            g_part[s] = t;
        }
        // no trailing sync needed: next-iter syncthreads gates smem reuse
    }

    // ---- exit handshake: last CTA of GRID finalizes ----
    if (threadIdx.x == 0) {
        __threadfence();
        unsigned v = atomicAdd(&g_done, 1u);
        amLast = (v == GRID - 1);
    }
    __syncthreads();

    if (amLast) {
        const int tid = threadIdx.x;
        double sum = 0.0;
        #pragma unroll
        for (int i = 0; i < NUNITS / 256; i++)
            sum += (double)((volatile float*)g_part)[tid + 256 * i];
        #pragma unroll
        for (int o = 16; o > 0; o >>= 1)
            sum += __shfl_xor_sync(0xffffffffu, sum, o);
        __shared__ double wd[8];
        if (lane == 0) wd[warp] = sum;
        __syncthreads();
        if (tid == 0) {
            double t = 0.0;
            #pragma unroll
            for (int i = 0; i < 8; i++) t += wd[i];
            out[0] = (float)(-t / NPIX);
            g_work = 0;                          // reset for next graph replay
            g_done = 0;
        }
    }
}

extern "C" void kernel_launch(void* const* d_in, const int* in_sizes, int n_in,
                              void* d_out, int out_size)
{
    (void)in_sizes; (void)n_in; (void)out_size;
    const float* x   = (const float*)d_in[0];   // [8,2,1024,1024] float32
    const int*   tgt = (const int*)d_in[1];     // [8,1,1024,1024] int32

    edge_loss_kernel<<<GRID, 256>>>(x, tgt, (float*)d_out);
}

// round 15
// speedup vs baseline: 1.0018x; 1.0018x over previous
#include <cuda_runtime.h>
#include <cstdint>

#define HGT    1024
#define WID    1024
#define RAD    5                     // 11x11 window radius
#define GRID   592                   // 148 SMs * 4 CTAs, one slab per CTA
#define MAXTY  14
#define MAXROWS (MAXTY + 2 * RAD)    // 24 halo rows max
#define NPIX   (8.0 * 1024.0 * 1024.0)

__device__ float    g_part[GRID];
__device__ unsigned g_done = 0;

__global__ __launch_bounds__(256, 4)
void edge_loss_kernel(const float* __restrict__ x, const int* __restrict__ tgt,
                      float* __restrict__ out)
{
    const int lane = threadIdx.x & 31;
    const int warp = threadIdx.x >> 5;

    // slab decode: per image, 62 slabs of 14 rows + 12 slabs of 13 rows = 1024
    const int s   = blockIdx.x;
    const int img = s / 74;
    const int j   = s % 74;
    const int ty  = (j < 62) ? 14 : 13;
    const int y0  = (j < 62) ? 14 * j : 868 + 13 * (j - 62);
    const int nrows = ty + 2 * RAD;

    __shared__ uint2    s_ha[MAXROWS][32];       // .x = horiz OR, .y = horiz AND
    __shared__ unsigned s_tw[MAXROWS][32];       // packed target bits
    __shared__ unsigned s_ew[MAXTY][32];         // per-output-row edge words
    __shared__ float    ws[8];

    // ---- Phase A (cooperative): pack halo rows, horizontal OR/AND +-5 ----
    const int* tbase = tgt + (size_t)img * HGT * WID;
    for (int i = warp; i < nrows; i += 8) {
        int row = y0 - RAD + i;
        unsigned w = 0u;
        if (row >= 0 && row < HGT) {
            const uint4* p = (const uint4*)(tbase + (size_t)row * WID + lane * 32);
            #pragma unroll
            for (int q = 0; q < 8; q++) {
                uint4 u = p[q];                  // target values are 0 or 1
                unsigned nib = u.x | (u.y << 1) | (u.z << 2) | (u.w << 3);
                w |= nib << (4 * q);
            }
        }
        unsigned wl = __shfl_up_sync(0xffffffffu, w, 1);
        unsigned wr = __shfl_down_sync(0xffffffffu, w, 1);
        if (lane == 0)  wl = 0u;                 // zero padding left
        if (lane == 31) wr = 0u;                 // zero padding right
        unsigned o = w, a = w;
        #pragma unroll
        for (int sh = 1; sh <= RAD; sh++) {
            unsigned r = __funnelshift_r(w, wr, sh);
            unsigned l = __funnelshift_l(wl, w, sh);
            o |= r | l;
            a &= r & l;
        }
        s_tw[i][lane] = w;
        s_ha[i][lane] = make_uint2(o, a);
    }
    __syncthreads();

    // ---- Vertical combine -> per-row edge words in smem ----
    for (int r = warp; r < ty; r += 8) {
        uint2 h0 = s_ha[r][lane];
        unsigned vo = h0.x, va = h0.y;
        #pragma unroll
        for (int d = 1; d <= 2 * RAD; d++) {
            uint2 hh = s_ha[r + d][lane];
            vo |= hh.x;
            va &= hh.y;
        }
        s_ew[r][lane] = vo ^ va;                 // edge: window not uniform
    }
    __syncthreads();

    // ---- Phase B: flat (row,k) work; warp takes contiguous ty iterations ----
    const float* xb0 = x + (size_t)img * 2 * HGT * WID;
    const float* xb1 = xb0 + (size_t)HGT * WID;
    const int m0 = warp * ty;
    const int wsel = lane >> 3;                  // smem word within row
    const int sh4  = 4 * (lane & 7);             // nibble within word

    #define XOFF(m) ((size_t)(y0 + ((m) >> 3)) * WID + 4 * lane + 128 * ((m) & 7))

    float4 b0[2], b1[2];                         // rolling 2-deep buffers
    b0[0] = __ldcs((const float4*)(xb0 + XOFF(m0)));
    b1[0] = __ldcs((const float4*)(xb1 + XOFF(m0)));
    b0[1] = __ldcs((const float4*)(xb0 + XOFF(m0 + 1)));
    b1[1] = __ldcs((const float4*)(xb1 + XOFF(m0 + 1)));

    float acc = 0.0f;
    for (int i = 0; i < ty; i++) {
        const int m = m0 + i;
        const int cur = i & 1;
        float4 v0 = b0[cur];
        float4 v1 = b1[cur];
        if (i + 2 < ty) {                        // prefetch iteration i+2
            b0[cur] = __ldcs((const float4*)(xb0 + XOFF(m + 2)));
            b1[cur] = __ldcs((const float4*)(xb1 + XOFF(m + 2)));
        }
        const int r = m >> 3, k = m & 7;
        unsigned e4 = (s_ew[r]      [4 * k + wsel] >> sh4) & 0xFu;
        unsigned t4 = (s_tw[r + RAD][4 * k + wsel] >> sh4) & 0xFu;
        #pragma unroll
        for (int jj = 0; jj < 4; jj++) {
            float a0 = (&v0.x)[jj];
            float a1 = (&v1.x)[jj];
            unsigned tbit = (t4 >> jj) & 1u;
            unsigned ebit = (e4 >> jj) & 1u;
            float xt = tbit ? a1 : a0;
            float xo = tbit ? a0 : a1;
            float mx  = fmaxf(a0, a1);
            float lse = mx + __logf(1.0f + __expf(-fabsf(a0 - a1)));
            float c_off = xt - lse;
            float c_on  = 0.95f * xt + 0.1f * xo - 1.05f * lse;
            acc += ebit ? c_on : c_off;
        }
    }
    #undef XOFF

    // ---- block reduction -> per-slab partial (deterministic) ----
    #pragma unroll
    for (int o = 16; o > 0; o >>= 1)
        acc += __shfl_xor_sync(0xffffffffu, acc, o);
    if (lane == 0) ws[warp] = acc;
    __syncthreads();

    __shared__ bool amLast;
    if (threadIdx.x == 0) {
        float t = 0.0f;
        #pragma unroll
        for (int i = 0; i < 8; i++) t += ws[i];
        g_part[blockIdx.x] = t;
        __threadfence();
        unsigned v = atomicAdd(&g_done, 1u);
        amLast = (v == GRID - 1);
    }
    __syncthreads();

    // ---- last block finalizes (deterministic; resets counter for replay) ----
    if (amLast) {
        const int tid = threadIdx.x;
        const volatile float* gp = (const volatile float*)g_part;
        double sum = (double)gp[tid] + (double)gp[tid + 256];
        if (tid < GRID - 512) sum += (double)gp[tid + 512];
        #pragma unroll
        for (int o = 16; o > 0; o >>= 1)
            sum += __shfl_xor_sync(0xffffffffu, sum, o);
        __shared__ double wd[8];
        if (lane == 0) wd[warp] = sum;
        __syncthreads();
        if (tid == 0) {
            double t = 0.0;
            #pragma unroll
            for (int i = 0; i < 8; i++) t += wd[i];
            out[0] = (float)(-t / NPIX);
            g_done = 0;                          // reset for next graph replay
        }
    }
}

extern "C" void kernel_launch(void* const* d_in, const int* in_sizes, int n_in,
                              void* d_out, int out_size)
{
    (void)in_sizes; (void)n_in; (void)out_size;
    const float* x   = (const float*)d_in[0];   // [8,2,1024,1024] float32
    const int*   tgt = (const int*)d_in[1];     // [8,1,1024,1024] int32

    edge_loss_kernel<<<GRID, 256>>>(x, tgt, (float*)d_out);
}

// round 16
// speedup vs baseline: 1.0847x; 1.0828x over previous
#include <cuda_runtime.h>
#include <cstdint>

#define HGT    1024
#define WID    1024
#define TY     8                     // output rows per CTA (2 per warp)
#define RAD    5                     // 11x11 window radius
#define NROWS  (TY + 2 * RAD)        // 18 halo rows per CTA
#define NBLK   1024                  // 8 images * 128 slabs; 8 CTAs/SM resident
#define NPIX   (8.0 * 1024.0 * 1024.0)

__device__ float    g_part[NBLK];
__device__ unsigned g_done = 0;

__global__ __launch_bounds__(128, 8)
void edge_loss_kernel(const float* __restrict__ x, const int* __restrict__ tgt,
                      float* __restrict__ out)
{
    const int lane = threadIdx.x & 31;
    const int warp = threadIdx.x >> 5;           // 0..3
    const int b    = blockIdx.x >> 7;            // image
    const int y0   = (blockIdx.x & 127) * TY;    // first output row of slab

    __shared__ uint2    s_ha[NROWS][32];         // .x = horiz OR, .y = horiz AND
    __shared__ unsigned s_tw[NROWS][32];

    // ---- Entry prefetch: first two Phase-B batches (overlap with Phase A) ----
    const int t0 = 2 * warp;
    const int yA = y0 + t0;
    const float* xbase = x + (size_t)b * 2 * HGT * WID;
    const float4* x0r[2] = { (const float4*)(xbase + (size_t)yA * WID),
                             (const float4*)(xbase + (size_t)(yA + 1) * WID) };
    const float4* x1r[2] = { (const float4*)(xbase + (size_t)(HGT + yA) * WID),
                             (const float4*)(xbase + (size_t)(HGT + yA + 1) * WID) };
    float4 b0[2], b1[2];                         // rolling 2-deep buffers
    b0[0] = __ldcs(&x0r[0][lane]);
    b1[0] = __ldcs(&x1r[0][lane]);
    b0[1] = __ldcs(&x0r[0][lane + 32]);
    b1[1] = __ldcs(&x1r[0][lane + 32]);

    // ---- Phase A (cooperative): pack 18 halo rows, horizontal OR/AND +-5 ----
    const int* tbase = tgt + (size_t)b * HGT * WID;
    #pragma unroll
    for (int i = warp; i < NROWS; i += 4) {
        int row = y0 - RAD + i;
        unsigned w = 0u;
        if (row >= 0 && row < HGT) {
            const uint4* p = (const uint4*)(tbase + (size_t)row * WID + lane * 32);
            #pragma unroll
            for (int q = 0; q < 8; q++) {
                uint4 u = p[q];                  // target values are 0 or 1
                unsigned nib = u.x | (u.y << 1) | (u.z << 2) | (u.w << 3);
                w |= nib << (4 * q);
            }
        }
        unsigned wl = __shfl_up_sync(0xffffffffu, w, 1);
        unsigned wr = __shfl_down_sync(0xffffffffu, w, 1);
        if (lane == 0)  wl = 0u;                 // zero padding left
        if (lane == 31) wr = 0u;                 // zero padding right
        unsigned o = w, a = w;
        #pragma unroll
        for (int sh = 1; sh <= RAD; sh++) {
            unsigned r = __funnelshift_r(w, wr, sh);
            unsigned l = __funnelshift_l(wl, w, sh);
            o |= r | l;
            a &= r & l;
        }
        s_tw[i][lane] = w;
        s_ha[i][lane] = make_uint2(o, a);
    }
    __syncthreads();

    // ---- Vertical combine: rows t0, t0+1 share 10 of 11 halo rows ----
    unsigned co = 0u, ca = 0xffffffffu;          // common: halo rows t0+1..t0+10
    #pragma unroll
    for (int d = 1; d <= 10; d++) {
        uint2 hh = s_ha[t0 + d][lane];
        co |= hh.x;
        ca &= hh.y;
    }
    uint2 hA = s_ha[t0][lane];
    uint2 hB = s_ha[t0 + 11][lane];
    unsigned ew0 = (co | hA.x) ^ (ca & hA.y);    // edge bits, row 0
    unsigned ew1 = (co | hB.x) ^ (ca & hB.y);    // edge bits, row 1
    unsigned tc0 = s_tw[t0 + RAD][lane];
    unsigned tc1 = s_tw[t0 + RAD + 1][lane];

    // ---- Assemble per-lane bit words: bit 4k+j = col 128k + 4*lane + j ----
    unsigned eb[2] = {0u, 0u}, tb[2] = {0u, 0u};
    const int src0 = lane >> 3, sh4 = 4 * (lane & 7);
    #pragma unroll
    for (int k = 0; k < 8; k++) {
        unsigned e0 = __shfl_sync(0xffffffffu, ew0, 4 * k + src0);
        unsigned t0s = __shfl_sync(0xffffffffu, tc0, 4 * k + src0);
        unsigned e1 = __shfl_sync(0xffffffffu, ew1, 4 * k + src0);
        unsigned t1s = __shfl_sync(0xffffffffu, tc1, 4 * k + src0);
        eb[0] |= ((e0 >> sh4) & 0xFu) << (4 * k);
        tb[0] |= ((t0s >> sh4) & 0xFu) << (4 * k);
        eb[1] |= ((e1 >> sh4) & 0xFu) << (4 * k);
        tb[1] |= ((t1s >> sh4) & 0xFu) << (4 * k);
    }

    // ---- Phase B: flat 16-iter loop (2 rows x 8 k), depth-2 prefetch ----
    float acc = 0.0f;
    #pragma unroll
    for (int m = 0; m < 16; m++) {
        const int cur = m & 1;
        float4 v0 = b0[cur];
        float4 v1 = b1[cur];
        if (m < 14) {                            // prefetch iteration m+2
            const int mn = m + 2;
            const int rn = mn >> 3, kn = mn & 7;
            b0[cur] = __ldcs(&x0r[rn][lane + 32 * kn]);
            b1[cur] = __ldcs(&x1r[rn][lane + 32 * kn]);
        }
        const int r = m >> 3, base = 4 * (m & 7);
        const unsigned ebw = eb[r], tbw = tb[r];
        #pragma unroll
        for (int j = 0; j < 4; j++) {
            float a0 = (&v0.x)[j];
            float a1 = (&v1.x)[j];
            unsigned tbit = (tbw >> (base + j)) & 1u;
            unsigned ebit = (ebw >> (base + j)) & 1u;
            float xt = tbit ? a1 : a0;
            float xo = tbit ? a0 : a1;
            float mx  = fmaxf(a0, a1);
            float lse = mx + __logf(1.0f + __expf(-fabsf(a0 - a1)));
            float c_off = xt - lse;
            float c_on  = 0.95f * xt + 0.1f * xo - 1.05f * lse;
            acc += ebit ? c_on : c_off;
        }
    }

    // ---- block reduction -> per-slab partial ----
    #pragma unroll
    for (int o = 16; o > 0; o >>= 1)
        acc += __shfl_xor_sync(0xffffffffu, acc, o);

    __shared__ float ws[4];
    if (lane == 0) ws[warp] = acc;
    __syncthreads();

    __shared__ bool amLast;
    if (threadIdx.x == 0) {
        float s = ws[0] + ws[1] + ws[2] + ws[3];
        g_part[blockIdx.x] = s;
        __threadfence();
        unsigned v = atomicAdd(&g_done, 1u);
        amLast = (v == NBLK - 1);
    }
    __syncthreads();

    // ---- last block finalizes (deterministic; resets counter for replay) ----
    if (amLast) {
        const int tid = threadIdx.x;
        double s = 0.0;
        #pragma unroll
        for (int i = 0; i < NBLK / 128; i++)
            s += (double)((volatile float*)g_part)[tid + 128 * i];
        #pragma unroll
        for (int o = 16; o > 0; o >>= 1)
            s += __shfl_xor_sync(0xffffffffu, s, o);
        __shared__ double wd[4];
        if (lane == 0) wd[warp] = s;
        __syncthreads();
        if (tid == 0) {
            double t = wd[0] + wd[1] + wd[2] + wd[3];
            out[0] = (float)(-t / NPIX);
            g_done = 0;                          // reset for next graph replay
        }
    }
}

extern "C" void kernel_launch(void* const* d_in, const int* in_sizes, int n_in,
                              void* d_out, int out_size)
{
    (void)in_sizes; (void)n_in; (void)out_size;
    const float* x   = (const float*)d_in[0];   // [8,2,1024,1024] float32
    const int*   tgt = (const int*)d_in[1];     // [8,1,1024,1024] int32

    edge_loss_kernel<<<NBLK, 128>>>(x, tgt, (float*)d_out);
}

// round 17
// speedup vs baseline: 1.4048x; 1.2951x over previous
#include <cuda_runtime.h>
#include <cstdint>

#define HGT   1024
#define WID   1024
#define NIMG  8
#define RAD   5                          // 11x11 window radius
#define WPR   32                         // words per row (1024/32)
#define NWORDS (NIMG * HGT * WPR)        // 262144 words = 1MB
#define NQUAD  (NIMG * HGT * WID / 4)    // 2097152 float4-quads
#define NB     1024
#define NPIX   (8.0 * 1024.0 * 1024.0)

__device__ unsigned g_pbits[NWORDS];     // packed target bits
__device__ unsigned g_ebits[NWORDS];     // packed edge bits
__device__ float    g_part[NB];
__device__ unsigned g_done = 0;

// ---- kernel 1: pack target {0,1} ints into bit words via ballot ----
__global__ __launch_bounds__(256)
void pack_kernel(const int* __restrict__ tgt)
{
    const int lane  = threadIdx.x & 31;
    const int gwarp = (blockIdx.x * 256 + threadIdx.x) >> 5;   // 0..8191
    // 8192 warps * 32 words = 262144: 8 iters of 4 consecutive words (512B read)
    #pragma unroll
    for (int it = 0; it < 8; it++) {
        const int w4 = gwarp * 4 + it * 32768;
        int v0 = tgt[(size_t)w4 * 32 + lane];
        int v1 = tgt[(size_t)w4 * 32 + 32 + lane];
        int v2 = tgt[(size_t)w4 * 32 + 64 + lane];
        int v3 = tgt[(size_t)w4 * 32 + 96 + lane];
        unsigned m0 = __ballot_sync(0xffffffffu, v0 & 1);
        unsigned m1 = __ballot_sync(0xffffffffu, v1 & 1);
        unsigned m2 = __ballot_sync(0xffffffffu, v2 & 1);
        unsigned m3 = __ballot_sync(0xffffffffu, v3 & 1);
        if (lane < 4)
            g_pbits[w4 + lane] = (lane == 0) ? m0 : (lane == 1) ? m1
                               : (lane == 2) ? m2 : m3;
    }
}

// ---- kernel 2: 11x11 uniformity test on packed bits -> edge bits ----
__global__ __launch_bounds__(256)
void edge_kernel()
{
    const int lane = threadIdx.x & 31;
    const int warp = threadIdx.x >> 5;               // 0..7
    const int b    = blockIdx.x >> 7;                // image
    const int y0   = (blockIdx.x & 127) * 8;         // 8 output rows per block

    __shared__ uint2 s_ha[18][32];                   // horiz OR / AND per halo row

    #pragma unroll
    for (int i = warp; i < 18; i += 8) {
        int row = y0 - RAD + i;
        unsigned w = (row >= 0 && row < HGT)
                   ? g_pbits[((size_t)b * HGT + row) * WPR + lane] : 0u;
        unsigned wl = __shfl_up_sync(0xffffffffu, w, 1);
        unsigned wr = __shfl_down_sync(0xffffffffu, w, 1);
        if (lane == 0)  wl = 0u;                     // zero padding left
        if (lane == 31) wr = 0u;                     // zero padding right
        unsigned o = w, a = w;
        #pragma unroll
        for (int s = 1; s <= RAD; s++) {
            unsigned r = __funnelshift_r(w, wr, s);
            unsigned l = __funnelshift_l(wl, w, s);
            o |= r | l;
            a &= r & l;
        }
        s_ha[i][lane] = make_uint2(o, a);
    }
    __syncthreads();

    unsigned vo = 0u, va = 0xffffffffu;              // warp owns output row y0+warp
    #pragma unroll
    for (int d = 0; d <= 2 * RAD; d++) {
        uint2 hh = s_ha[warp + d][lane];
        vo |= hh.x;
        va &= hh.y;
    }
    g_ebits[((size_t)b * HGT + y0 + warp) * WPR + lane] = vo ^ va;
}

// ---- kernel 3: fused log-softmax label-smoothing loss (pure stream) ----
__global__ __launch_bounds__(256)
void loss_kernel(const float* __restrict__ x, float* __restrict__ out)
{
    const int tid0 = blockIdx.x * 256 + threadIdx.x;
    float acc = 0.0f;

    // 2M quads / 262144 threads = 8 exact iterations
    #pragma unroll 4
    for (int it = 0; it < 8; it++) {
        const int g = tid0 + it * (NB * 256);
        const int p = g << 2;                        // first pixel of quad
        const int img = p >> 20;
        const int q   = p & 1048575;
        const float* x0p = x + (size_t)img * 2097152 + q;
        float4 v0 = __ldcs((const float4*)x0p);
        float4 v1 = __ldcs((const float4*)(x0p + 1048576));
        const int sh = (g & 7) * 4;
        unsigned e4 = (g_ebits[g >> 3] >> sh) & 0xFu;
        unsigned t4 = (g_pbits[g >> 3] >> sh) & 0xFu;
        #pragma unroll
        for (int j = 0; j < 4; j++) {
            float a0 = (&v0.x)[j];
            float a1 = (&v1.x)[j];
            unsigned tbit = (t4 >> j) & 1u;
            unsigned ebit = (e4 >> j) & 1u;
            float xt = tbit ? a1 : a0;
            float xo = tbit ? a0 : a1;
            float mx  = fmaxf(a0, a1);
            float lse = mx + __logf(1.0f + __expf(-fabsf(a0 - a1)));
            float c_off = xt - lse;
            float c_on  = 0.95f * xt + 0.1f * xo - 1.05f * lse;
            acc += ebit ? c_on : c_off;
        }
    }

    // ---- block reduction -> per-block partial ----
    const int lane = threadIdx.x & 31;
    const int warp = threadIdx.x >> 5;
    #pragma unroll
    for (int o = 16; o > 0; o >>= 1)
        acc += __shfl_xor_sync(0xffffffffu, acc, o);

    __shared__ float ws[8];
    if (lane == 0) ws[warp] = acc;
    __syncthreads();

    __shared__ bool amLast;
    if (threadIdx.x == 0) {
        float s = 0.0f;
        #pragma unroll
        for (int i = 0; i < 8; i++) s += ws[i];
        g_part[blockIdx.x] = s;
        __threadfence();
        unsigned v = atomicAdd(&g_done, 1u);
        amLast = (v == NB - 1);
    }
    __syncthreads();

    if (amLast) {
        const int tid = threadIdx.x;
        double s = 0.0;
        #pragma unroll
        for (int i = 0; i < NB / 256; i++)
            s += (double)((volatile float*)g_part)[tid + 256 * i];
        #pragma unroll
        for (int o = 16; o > 0; o >>= 1)
            s += __shfl_xor_sync(0xffffffffu, s, o);
        __shared__ double wd[8];
        if (lane == 0) wd[warp] = s;
        __syncthreads();
        if (tid == 0) {
            double t = 0.0;
            #pragma unroll
            for (int i = 0; i < 8; i++) t += wd[i];
            out[0] = (float)(-t / NPIX);
            g_done = 0;                              // reset for next graph replay
        }
    }
}

extern "C" void kernel_launch(void* const* d_in, const int* in_sizes, int n_in,
                              void* d_out, int out_size)
{
    (void)in_sizes; (void)n_in; (void)out_size;
    const float* x   = (const float*)d_in[0];        // [8,2,1024,1024] float32
    const int*   tgt = (const int*)d_in[1];          // [8,1,1024,1024] int32

    pack_kernel<<<NB, 256>>>(tgt);
    edge_kernel<<<NB, 256>>>();
    loss_kernel<<<NB, 256>>>(x, (float*)d_out);
}